// round 10
// baseline (speedup 1.0000x reference)
#include <cuda_runtime.h>
#include <cuda_fp16.h>
#include <cstdint>

// CosinePrediction: cos[e] = <u[src[e]], v[dst[e]]> / (||u||*||v||)
// Phase 1 (single fused launch): L2-normalize ALL rows of both tensors,
//   store fp16 rows (128 B/row) in scratch.
// Phase 2: PERSISTENT gather, 8 lanes per edge-PAIR, software-pipelined:
//   row loads for the next pair are issued one full iteration before use
//   (double-buffered registers, manual unroll-by-2), indices prefetched
//   two iterations ahead. Depth-2 fp16 dot accumulation.

static constexpr int D = 64;
static constexpr int MAX_ROWS = 100000;       // N_U = N_I = 100000 (fixed problem shape)
static constexpr int THREADS = 256;
static constexpr int GATHER_BLOCKS = 740;     // 5 blocks/SM * 148 SMs, persistent

// fp16 normalized rows (25.6 MB total scratch)
__device__ __half g_nu[(size_t)MAX_ROWS * D];
__device__ __half g_ni[(size_t)MAX_ROWS * D];

// ---------------- Phase 1: fused normalize + fp16 convert ----------------
__device__ __forceinline__ void norm_store(
    const float4 a, const float4 b, float rn, __half* __restrict__ drow, int lane)
{
    __half2 h[4];
    h[0] = __floats2half2_rn(a.x * rn, a.y * rn);
    h[1] = __floats2half2_rn(a.z * rn, a.w * rn);
    h[2] = __floats2half2_rn(b.x * rn, b.y * rn);
    h[3] = __floats2half2_rn(b.z * rn, b.w * rn);
    *reinterpret_cast<uint2*>(drow + 4 * lane)      = *reinterpret_cast<uint2*>(&h[0]);
    *reinterpret_cast<uint2*>(drow + 32 + 4 * lane) = *reinterpret_cast<uint2*>(&h[2]);
}

__global__ __launch_bounds__(THREADS) void normalize_fused_kernel(
    const float* __restrict__ h_user,
    const float* __restrict__ h_item,
    int n_user, int n_total)
{
    const int gid  = blockIdx.x * THREADS + threadIdx.x;
    const int p    = gid >> 3;           // row-pair index
    const int lane = gid & 7;
    const int r0   = p * 2;
    if (r0 >= n_total) return;
    const int r1 = r0 + 1;

    const float* src0 = (r0 < n_user) ? (h_user + (long long)r0 * D)
                                      : (h_item + (long long)(r0 - n_user) * D);
    __half* dst0 = (r0 < n_user) ? (g_nu + (long long)r0 * D)
                                 : (g_ni + (long long)(r0 - n_user) * D);

    const bool have1 = r1 < n_total;
    const float* src1 = src0;
    __half* dst1 = dst0;
    if (have1) {
        src1 = (r1 < n_user) ? (h_user + (long long)r1 * D)
                             : (h_item + (long long)(r1 - n_user) * D);
        dst1 = (r1 < n_user) ? (g_nu + (long long)r1 * D)
                             : (g_ni + (long long)(r1 - n_user) * D);
    }

    const float4 a0 = __ldg(reinterpret_cast<const float4*>(src0) + lane);
    const float4 b0 = __ldg(reinterpret_cast<const float4*>(src0) + lane + 8);
    const float4 a1 = __ldg(reinterpret_cast<const float4*>(src1) + lane);
    const float4 b1 = __ldg(reinterpret_cast<const float4*>(src1) + lane + 8);

    float n0 = a0.x * a0.x;
    n0 = fmaf(a0.y, a0.y, n0); n0 = fmaf(a0.z, a0.z, n0); n0 = fmaf(a0.w, a0.w, n0);
    n0 = fmaf(b0.x, b0.x, n0); n0 = fmaf(b0.y, b0.y, n0);
    n0 = fmaf(b0.z, b0.z, n0); n0 = fmaf(b0.w, b0.w, n0);

    float n1 = a1.x * a1.x;
    n1 = fmaf(a1.y, a1.y, n1); n1 = fmaf(a1.z, a1.z, n1); n1 = fmaf(a1.w, a1.w, n1);
    n1 = fmaf(b1.x, b1.x, n1); n1 = fmaf(b1.y, b1.y, n1);
    n1 = fmaf(b1.z, b1.z, n1); n1 = fmaf(b1.w, b1.w, n1);

    #pragma unroll
    for (int o = 4; o > 0; o >>= 1) {
        n0 += __shfl_xor_sync(0xFFFFFFFFu, n0, o);
        n1 += __shfl_xor_sync(0xFFFFFFFFu, n1, o);
    }

    norm_store(a0, b0, rsqrtf(n0), dst0, lane);
    if (have1) norm_store(a1, b1, rsqrtf(n1), dst1, lane);
}

// ---------------- Phase 2: persistent pipelined gather ----------------
__device__ __forceinline__ float dot8h(uint4 w, uint4 z)
{
    const __half2* wh = reinterpret_cast<const __half2*>(&w);
    const __half2* zh = reinterpret_cast<const __half2*>(&z);
    const __half2 p01 = __hfma2(wh[0], zh[0], __hmul2(wh[1], zh[1]));
    const __half2 p23 = __hfma2(wh[2], zh[2], __hmul2(wh[3], zh[3]));
    const float2 f01 = __half22float2(p01);
    const float2 f23 = __half22float2(p23);
    return (f01.x + f01.y) + (f23.x + f23.y);
}

__device__ __forceinline__ void load_pair_rows(
    int2 s, int2 d, int lane, uint4& w0, uint4& z0, uint4& w1, uint4& z1)
{
    w0 = __ldg(reinterpret_cast<const uint4*>(g_nu + (long long)s.x * D) + lane);
    z0 = __ldg(reinterpret_cast<const uint4*>(g_ni + (long long)d.x * D) + lane);
    w1 = __ldg(reinterpret_cast<const uint4*>(g_nu + (long long)s.y * D) + lane);
    z1 = __ldg(reinterpret_cast<const uint4*>(g_ni + (long long)d.y * D) + lane);
}

__device__ __forceinline__ void reduce_store_pair(
    uint4 w0, uint4 z0, uint4 w1, uint4 z1, int lane, float* __restrict__ out, int p)
{
    float c0 = dot8h(w0, z0);
    float c1 = dot8h(w1, z1);
    #pragma unroll
    for (int o = 4; o > 0; o >>= 1) {
        c0 += __shfl_xor_sync(0xFFFFFFFFu, c0, o);
        c1 += __shfl_xor_sync(0xFFFFFFFFu, c1, o);
    }
    if (lane == 0) {
        float2 r; r.x = c0; r.y = c1;
        *reinterpret_cast<float2*>(out + p * 2) = r;
    }
}

__global__ __launch_bounds__(THREADS, 5) void cosine_gather_kernel(
    const int* __restrict__ src_idx,
    const int* __restrict__ dst_idx,
    float* __restrict__ out,
    int E)
{
    const int gid    = blockIdx.x * THREADS + threadIdx.x;
    const int lane   = gid & 7;
    const int stride = (GATHER_BLOCKS * THREADS) >> 3;   // pair-groups per sweep
    const int npairs = E >> 1;                           // full pairs

    int p = gid >> 3;
    if (p < npairs) {
        const int2* __restrict__ srcp = reinterpret_cast<const int2*>(src_idx);
        const int2* __restrict__ dstp = reinterpret_cast<const int2*>(dst_idx);

        // ---- prime: rows for p in buffer A, indices for p+stride ----
        int2 s0 = __ldg(srcp + p);
        int2 d0 = __ldg(dstp + p);
        uint4 wA0, zA0, wA1, zA1;
        load_pair_rows(s0, d0, lane, wA0, zA0, wA1, zA1);

        int pn = p + stride;
        bool moren = pn < npairs;
        int2 sN = s0, dN = d0;
        if (moren) { sN = __ldg(srcp + pn); dN = __ldg(dstp + pn); }

        uint4 wB0, zB0, wB1, zB1;

        while (true) {
            // ================= phase A: compute A, load B =================
            if (moren) load_pair_rows(sN, dN, lane, wB0, zB0, wB1, zB1);
            {
                const int pn2 = pn + stride;
                const bool moren2 = moren && (pn2 < npairs);
                if (moren2) { sN = __ldg(srcp + pn2); dN = __ldg(dstp + pn2); }
                reduce_store_pair(wA0, zA0, wA1, zA1, lane, out, p);
                if (!moren) break;
                p = pn; pn = pn2; moren = moren2;
            }

            // ================= phase B: compute B, load A =================
            if (moren) load_pair_rows(sN, dN, lane, wA0, zA0, wA1, zA1);
            {
                const int pn2 = pn + stride;
                const bool moren2 = moren && (pn2 < npairs);
                if (moren2) { sN = __ldg(srcp + pn2); dN = __ldg(dstp + pn2); }
                reduce_store_pair(wB0, zB0, wB1, zB1, lane, out, p);
                if (!moren) break;
                p = pn; pn = pn2; moren = moren2;
            }
        }
    }

    // Tail edge (E odd), handled by the first lane-group of block 0.
    if (blockIdx.x == 0 && (threadIdx.x >> 3) == 0) {
        for (int e = npairs * 2; e < E; e++) {
            const int s = __ldg(src_idx + e);
            const int d = __ldg(dst_idx + e);
            const uint4 w = __ldg(reinterpret_cast<const uint4*>(g_nu + (long long)s * D) + lane);
            const uint4 z = __ldg(reinterpret_cast<const uint4*>(g_ni + (long long)d * D) + lane);
            float c = dot8h(w, z);
            #pragma unroll
            for (int o = 4; o > 0; o >>= 1) c += __shfl_xor_sync(0xFFFFFFFFu, c, o);
            if (lane == 0) out[e] = c;
        }
    }
}

extern "C" void kernel_launch(void* const* d_in, const int* in_sizes, int n_in,
                              void* d_out, int out_size)
{
    const float* h_user = (const float*)d_in[0];
    const float* h_item = (const float*)d_in[1];
    const int*   src    = (const int*)d_in[2];
    const int*   dst    = (const int*)d_in[3];
    float*       out    = (float*)d_out;

    const int N_U = in_sizes[0] / D;
    const int N_I = in_sizes[1] / D;
    const int E   = in_sizes[2];
    const int N_T = N_U + N_I;

    {
        const int pairs = (N_T + 1) / 2;
        const long long t = (long long)pairs * 8;
        normalize_fused_kernel<<<(int)((t + THREADS - 1) / THREADS), THREADS>>>(
            h_user, h_item, N_U, N_T);
    }
    cosine_gather_kernel<<<GATHER_BLOCKS, THREADS>>>(src, dst, out, E);
}